// round 13
// baseline (speedup 1.0000x reference)
#include <cuda_runtime.h>
#include <cuda_fp16.h>

#define Bq   512
#define Tt   365
#define Ff   16
#define Hh   256
#define G4   1024
#define NCg  32      // CTAs (16 batch rows each)
#define MB   16      // batch rows per CTA
#define NT   1024    // 32 warps; warp w owns packed cols [w*32, w*32+32)
#define K1T  17      // layer-1 k-tiles (272 = 16 x + 256 h1)
#define K2T  32      // layer-2 k-tiles (512 = 256 h1 + 256 h2)
#define HST  536     // unified buffer col stride (halves): [x 16 | h1 256 | h2 256 | pad]
#define H1OFF 16
#define H2OFF 272

// ---------------------------------------------------------------------------
// Pre-packed fp16 B fragments (m16n8k16 .col), GATE-INTERLEAVED col order:
//   packed col P = w*32 + n ; gate = n&3 (i,f,g,o), unit = w*8 + (n>>2)
//   original torch col oc = gate*256 + unit
//   frag idx ((kt*32 + w)*2 + p)*32 + lane -> uint4 = 8 halves:
//     halves 0..3 = tile 2p  (col w*32+16p+(lane>>2)): B[k0+2m],[k0+2m+1],[k0+2m+8],[k0+2m+9]
//     halves 4..7 = tile 2p+1 (col +8), same k rows      (m = lane&3)
// ---------------------------------------------------------------------------
__device__ __align__(16) __half g_wb1[(Ff + Hh) * G4];
__device__ __align__(16) __half g_wb2[2 * Hh * G4];
__device__ float g_b1p[G4];   // biases in packed col order
__device__ float g_b2p[G4];

// fast activations: MUFU-based, ~1e-6 rel err
__device__ __forceinline__ float sigf(float x) {
    return __fdividef(1.0f, 1.0f + __expf(-x));
}
__device__ __forceinline__ float tanhg(float x) {
    return __fdividef(2.0f, 1.0f + __expf(-2.0f * x)) - 1.0f;
}

__device__ __forceinline__ unsigned s2u(const void* p) {
    unsigned a;
    asm("{ .reg .u64 t; cvta.to.shared.u64 t, %1; cvt.u32.u64 %0, t; }" : "=r"(a) : "l"(p));
    return a;
}
__device__ __forceinline__ void ldsm4(unsigned& a0, unsigned& a1, unsigned& a2, unsigned& a3,
                                      unsigned addr) {
    asm volatile("ldmatrix.sync.aligned.m8n8.x4.shared.b16 {%0,%1,%2,%3}, [%4];"
                 : "=r"(a0), "=r"(a1), "=r"(a2), "=r"(a3) : "r"(addr));
}
__device__ __forceinline__ void mma16816(float& d0, float& d1, float& d2, float& d3,
                                         unsigned a0, unsigned a1, unsigned a2, unsigned a3,
                                         unsigned b0, unsigned b1) {
    asm volatile("mma.sync.aligned.m16n8k16.row.col.f32.f16.f16.f32 "
                 "{%0,%1,%2,%3}, {%4,%5,%6,%7}, {%8,%9}, {%0,%1,%2,%3};"
                 : "+f"(d0), "+f"(d1), "+f"(d2), "+f"(d3)
                 : "r"(a0), "r"(a1), "r"(a2), "r"(a3), "r"(b0), "r"(b1));
}
__device__ __forceinline__ void sts16(unsigned addr, __half v) {
    asm volatile("st.shared.b16 [%0], %1;" :: "r"(addr), "h"(__half_as_ushort(v)) : "memory");
}

// ---------------------------------------------------------------------------
// Prep: pack B fragments (gate-interleaved, 32 cols per warp) + packed biases.
// ---------------------------------------------------------------------------
__global__ void prep_kernel(const float* __restrict__ wih1, const float* __restrict__ whh1,
                            const float* __restrict__ bih1, const float* __restrict__ bhh1,
                            const float* __restrict__ wih2, const float* __restrict__ whh2,
                            const float* __restrict__ bih2, const float* __restrict__ bhh2) {
    int idx = blockIdx.x * blockDim.x + threadIdx.x;   // over K2T*32*2*32 = 65536
    int lane = idx & 31, p = (idx >> 5) & 1, w = (idx >> 6) & 31, kt = idx >> 11;
    int m = lane & 3, c = lane >> 2;
    int k0 = kt * 16;
    int nA = p * 16 + c, nB = nA + 8;
    int ocA = (nA & 3) * 256 + w * 8 + (nA >> 2);
    int ocB = (nB & 3) * 256 + w * 8 + (nB >> 2);
    int ks[4] = {k0 + 2 * m, k0 + 2 * m + 1, k0 + 2 * m + 8, k0 + 2 * m + 9};

    if (kt < K2T) {   // layer 2: K = 512 (h1 rows 0..255, h2 rows 256..511)
        __align__(16) __half h[8];
        #pragma unroll
        for (int j = 0; j < 4; ++j) {
            int k = ks[j];
            float vA = (k < Hh) ? wih2[ocA * Hh + k] : whh2[ocA * Hh + (k - Hh)];
            float vB = (k < Hh) ? wih2[ocB * Hh + k] : whh2[ocB * Hh + (k - Hh)];
            h[j]     = __float2half_rn(vA);
            h[4 + j] = __float2half_rn(vB);
        }
        *((uint4*)g_wb2 + idx) = *(const uint4*)h;
    }
    if (kt < K1T) {   // layer 1: K = 272 (x rows 0..15, h1 rows 16..271)
        __align__(16) __half h[8];
        #pragma unroll
        for (int j = 0; j < 4; ++j) {
            int k = ks[j];
            float vA = (k < Ff) ? wih1[ocA * Ff + k] : whh1[ocA * Hh + (k - Ff)];
            float vB = (k < Ff) ? wih1[ocB * Ff + k] : whh1[ocB * Hh + (k - Ff)];
            h[j]     = __float2half_rn(vA);
            h[4 + j] = __float2half_rn(vB);
        }
        *((uint4*)g_wb1 + idx) = *(const uint4*)h;
    }
    if (idx < G4) {
        int P = idx, wp = P >> 5, n = P & 31;
        int oc = (n & 3) * 256 + wp * 8 + (n >> 2);
        g_b1p[P] = bih1[oc] + bhh1[oc];
        g_b2p[P] = bih2[oc] + bhh2[oc];
    }
}

// ---------------------------------------------------------------------------
// Fused 2-layer LSTM, tensor cores, 32 warps, in-register gate update.
// ---------------------------------------------------------------------------
__global__ void __launch_bounds__(NT, 1)
lstm_kernel(const float* __restrict__ x,
            const float* __restrict__ wlin, const float* __restrict__ blin,
            float* __restrict__ out) {
    __shared__ __align__(16) __half buf[MB * HST];   // [16 rows][x|h1|h2]

    const int tid  = threadIdx.x;
    const int lane = tid & 31;
    const int w    = tid >> 5;
    const int m    = lane & 3;
    const int g    = lane >> 2;
    const bool modd = (m & 1);
    const int b0   = blockIdx.x * MB;

    for (int i = tid; i < MB * HST; i += NT) buf[i] = __ushort_as_half(0);

    float c1[4], c2[4];
    #pragma unroll
    for (int j = 0; j < 4; ++j) { c1[j] = 0.f; c2[j] = 0.f; }

    const unsigned sbase = s2u(buf);
    const int lr  = (lane & 7) + 8 * ((lane >> 3) & 1);
    const int lc8 = (lane >> 4) * 8;
    const unsigned aBase = sbase + (unsigned)(lr * HST + lc8) * 2u;

    const uint4* wb1 = (const uint4*)g_wb1 + w * 64 + lane;   // + kt*2048 + p*32
    const uint4* wb2 = (const uint4*)g_wb2 + w * 64 + lane;

    // update identity: row = g (m even) / g+8 (m odd); unit = w*8 + 2nt + (m>>1)
    const int urow = modd ? (g + 8) : g;
    const unsigned h1addr = sbase + (unsigned)(urow * HST + H1OFF + w * 8 + (m >> 1)) * 2u;
    const unsigned h2addr = sbase + (unsigned)(urow * HST + H2OFF + w * 8 + (m >> 1)) * 2u;

    // stage x(0)
    if (tid < MB * Ff) {
        int b = tid >> 4, f = tid & 15;
        buf[b * HST + f] = __float2half_rn(__ldg(&x[((size_t)(b0 + b) * Tt) * Ff + f]));
    }
    __syncthreads();

    float acc[4][4];

    for (int t = 0; t < Tt; ++t) {
        // ================= LAYER 1 gates =================
        #pragma unroll
        for (int nt = 0; nt < 4; ++nt) {
            float2 bv = __ldg((const float2*)&g_b1p[w * 32 + 8 * nt + 2 * m]);
            acc[nt][0] = bv.x; acc[nt][1] = bv.y; acc[nt][2] = bv.x; acc[nt][3] = bv.y;
        }
        for (int kt = 0; kt < K1T; ++kt) {
            uint4 bv0 = __ldg(wb1 + kt * 2048);
            uint4 bv1 = __ldg(wb1 + kt * 2048 + 32);
            unsigned a0, a1, a2, a3;
            ldsm4(a0, a1, a2, a3, aBase + (unsigned)(kt * 16) * 2u);
            mma16816(acc[0][0], acc[0][1], acc[0][2], acc[0][3], a0, a1, a2, a3, bv0.x, bv0.y);
            mma16816(acc[1][0], acc[1][1], acc[1][2], acc[1][3], a0, a1, a2, a3, bv0.z, bv0.w);
            mma16816(acc[2][0], acc[2][1], acc[2][2], acc[2][3], a0, a1, a2, a3, bv1.x, bv1.y);
            mma16816(acc[3][0], acc[3][1], acc[3][2], acc[3][3], a0, a1, a2, a3, bv1.z, bv1.w);
        }
        __syncthreads();   // all reads of h1(old)/x done

        // ---- update 1 (registers) + write h1 ----
        #pragma unroll
        for (int nt = 0; nt < 4; ++nt) {
            float t0 = __shfl_xor_sync(0xffffffffu, acc[nt][0], 1);
            float t1 = __shfl_xor_sync(0xffffffffu, acc[nt][1], 1);
            float t2 = __shfl_xor_sync(0xffffffffu, acc[nt][2], 1);
            float t3 = __shfl_xor_sync(0xffffffffu, acc[nt][3], 1);
            float zi = modd ? t2 : acc[nt][0];
            float zf = modd ? t3 : acc[nt][1];
            float zg = modd ? acc[nt][2] : t0;
            float zo = modd ? acc[nt][3] : t1;
            c1[nt] = sigf(zf) * c1[nt] + sigf(zi) * tanhg(zg);
            float h = sigf(zo) * tanhg(c1[nt]);
            sts16(h1addr + 4u * nt, __float2half_rn(h));
        }
        __syncthreads();   // h1(new) visible

        // ================= LAYER 2 gates =================
        #pragma unroll
        for (int nt = 0; nt < 4; ++nt) {
            float2 bv = __ldg((const float2*)&g_b2p[w * 32 + 8 * nt + 2 * m]);
            acc[nt][0] = bv.x; acc[nt][1] = bv.y; acc[nt][2] = bv.x; acc[nt][3] = bv.y;
        }
        for (int kt = 0; kt < K2T; ++kt) {
            uint4 bv0 = __ldg(wb2 + kt * 2048);
            uint4 bv1 = __ldg(wb2 + kt * 2048 + 32);
            unsigned a0, a1, a2, a3;
            ldsm4(a0, a1, a2, a3, aBase + (unsigned)(H1OFF + kt * 16) * 2u);
            mma16816(acc[0][0], acc[0][1], acc[0][2], acc[0][3], a0, a1, a2, a3, bv0.x, bv0.y);
            mma16816(acc[1][0], acc[1][1], acc[1][2], acc[1][3], a0, a1, a2, a3, bv0.z, bv0.w);
            mma16816(acc[2][0], acc[2][1], acc[2][2], acc[2][3], a0, a1, a2, a3, bv1.x, bv1.y);
            mma16816(acc[3][0], acc[3][1], acc[3][2], acc[3][3], a0, a1, a2, a3, bv1.z, bv1.w);
        }
        __syncthreads();   // all reads of h1(new)/h2(old) done

        // ---- update 2 (registers) + write h2 + stage x(t+1) ----
        #pragma unroll
        for (int nt = 0; nt < 4; ++nt) {
            float t0 = __shfl_xor_sync(0xffffffffu, acc[nt][0], 1);
            float t1 = __shfl_xor_sync(0xffffffffu, acc[nt][1], 1);
            float t2 = __shfl_xor_sync(0xffffffffu, acc[nt][2], 1);
            float t3 = __shfl_xor_sync(0xffffffffu, acc[nt][3], 1);
            float zi = modd ? t2 : acc[nt][0];
            float zf = modd ? t3 : acc[nt][1];
            float zg = modd ? acc[nt][2] : t0;
            float zo = modd ? acc[nt][3] : t1;
            c2[nt] = sigf(zf) * c2[nt] + sigf(zi) * tanhg(zg);
            float h = sigf(zo) * tanhg(c2[nt]);
            sts16(h2addr + 4u * nt, __float2half_rn(h));
        }
        if (tid < MB * Ff && t + 1 < Tt) {
            int b = tid >> 4, f = tid & 15;
            buf[b * HST + f] =
                __float2half_rn(__ldg(&x[((size_t)(b0 + b) * Tt + (t + 1)) * Ff + f]));
        }
        __syncthreads();   // h2(new) + x(t+1) visible
    }

    // ================= linear head: warp w (<16) -> batch row w =================
    if (w < MB) {
        float s = 0.f;
        #pragma unroll
        for (int u = lane; u < Hh; u += 32)
            s += __half2float(buf[w * HST + H2OFF + u]) * __ldg(&wlin[u]);
        #pragma unroll
        for (int off = 16; off; off >>= 1) s += __shfl_xor_sync(0xffffffffu, s, off);
        if (lane == 0) out[b0 + w] = s + blin[0];
    }
}

// ---------------------------------------------------------------------------
extern "C" void kernel_launch(void* const* d_in, const int* in_sizes, int n_in,
                              void* d_out, int out_size) {
    const float* x    = (const float*)d_in[0];
    const float* wih1 = (const float*)d_in[1];
    const float* whh1 = (const float*)d_in[2];
    const float* bih1 = (const float*)d_in[3];
    const float* bhh1 = (const float*)d_in[4];
    const float* wih2 = (const float*)d_in[5];
    const float* whh2 = (const float*)d_in[6];
    const float* bih2 = (const float*)d_in[7];
    const float* bhh2 = (const float*)d_in[8];
    const float* wlin = (const float*)d_in[9];
    const float* blin = (const float*)d_in[10];
    float* out = (float*)d_out;

    prep_kernel<<<(K2T * 32 * 2 * 32 + 255) / 256, 256>>>(wih1, whh1, bih1, bhh1,
                                                          wih2, whh2, bih2, bhh2);
    lstm_kernel<<<NCg, NT>>>(x, wlin, blin, out);
}

// round 14
// speedup vs baseline: 1.7075x; 1.7075x over previous
#include <cuda_runtime.h>
#include <cuda_fp16.h>

#define Bq   512
#define Tt   365
#define Ff   16
#define Hh   256
#define G4   1024
#define CLU  2       // CTAs per cluster (gate-col split)
#define NCg  64      // CTAs total (32 clusters x 2)
#define MB   16      // batch rows per cluster (= per CTA, shared)
#define NT   512     // 16 warps; warp owns 32 packed cols of this CTA's 512
#define K1T  17      // layer-1 k-tiles (272 = 16 x + 256 h1)
#define K2T  32      // layer-2 k-tiles (512 = 256 h1 + 256 h2)
#define HST  536     // buffer col stride (halves): [x 16 | h1 256 | h2 256 | pad]
#define H1OFF 16
#define H2OFF 272

// ---------------------------------------------------------------------------
// fp16 B fragments (m16n8k16 .col), gate-interleaved, CLUSTER-SPLIT col order:
//   packed col P = r*512 + w*32 + n ; gate = n&3, unit = r*128 + w*8 + (n>>2)
//   frag uint4 idx = kt*2048 + r*1024 + w*64 + p*32 + lane
// ---------------------------------------------------------------------------
__device__ __align__(16) __half g_wb1[(Ff + Hh) * G4];
__device__ __align__(16) __half g_wb2[2 * Hh * G4];
__device__ float g_b1p[G4];
__device__ float g_b2p[G4];

__device__ __forceinline__ float sigf(float x) {
    return __fdividef(1.0f, 1.0f + __expf(-x));
}
__device__ __forceinline__ float tanhg(float x) {
    return __fdividef(2.0f, 1.0f + __expf(-2.0f * x)) - 1.0f;
}
__device__ __forceinline__ unsigned s2u(const void* p) {
    unsigned a;
    asm("{ .reg .u64 t; cvta.to.shared.u64 t, %1; cvt.u32.u64 %0, t; }" : "=r"(a) : "l"(p));
    return a;
}
__device__ __forceinline__ void ldsm4(unsigned& a0, unsigned& a1, unsigned& a2, unsigned& a3,
                                      unsigned addr) {
    asm volatile("ldmatrix.sync.aligned.m8n8.x4.shared.b16 {%0,%1,%2,%3}, [%4];"
                 : "=r"(a0), "=r"(a1), "=r"(a2), "=r"(a3) : "r"(addr));
}
__device__ __forceinline__ void mma16816(float& d0, float& d1, float& d2, float& d3,
                                         unsigned a0, unsigned a1, unsigned a2, unsigned a3,
                                         unsigned b0, unsigned b1) {
    asm volatile("mma.sync.aligned.m16n8k16.row.col.f32.f16.f16.f32 "
                 "{%0,%1,%2,%3}, {%4,%5,%6,%7}, {%8,%9}, {%0,%1,%2,%3};"
                 : "+f"(d0), "+f"(d1), "+f"(d2), "+f"(d3)
                 : "r"(a0), "r"(a1), "r"(a2), "r"(a3), "r"(b0), "r"(b1));
}
__device__ __forceinline__ void sts16(unsigned addr, __half v) {
    asm volatile("st.shared.b16 [%0], %1;" :: "r"(addr), "h"(__half_as_ushort(v)) : "memory");
}
__device__ __forceinline__ void cluster_sync_all() {
    asm volatile("barrier.cluster.arrive.aligned;" ::: "memory");
    asm volatile("barrier.cluster.wait.aligned;"   ::: "memory");
}

// ---------------------------------------------------------------------------
// Prep: pack B fragments (cluster-split cols) + packed biases.
// ---------------------------------------------------------------------------
__global__ void prep_kernel(const float* __restrict__ wih1, const float* __restrict__ whh1,
                            const float* __restrict__ bih1, const float* __restrict__ bhh1,
                            const float* __restrict__ wih2, const float* __restrict__ whh2,
                            const float* __restrict__ bih2, const float* __restrict__ bhh2) {
    int idx = blockIdx.x * blockDim.x + threadIdx.x;   // uint4 index, over K2T*2048 = 65536
    int lane = idx & 31, p = (idx >> 5) & 1, w = (idx >> 6) & 15;
    int r = (idx >> 10) & 1, kt = idx >> 11;
    int m = lane & 3, c = lane >> 2;
    int k0 = kt * 16;
    int nA = p * 16 + c, nB = nA + 8;
    int ocA = (nA & 3) * 256 + r * 128 + w * 8 + (nA >> 2);
    int ocB = (nB & 3) * 256 + r * 128 + w * 8 + (nB >> 2);
    int ks[4] = {k0 + 2 * m, k0 + 2 * m + 1, k0 + 2 * m + 8, k0 + 2 * m + 9};

    if (kt < K2T) {
        __align__(16) __half h[8];
        #pragma unroll
        for (int j = 0; j < 4; ++j) {
            int k = ks[j];
            float vA = (k < Hh) ? wih2[ocA * Hh + k] : whh2[ocA * Hh + (k - Hh)];
            float vB = (k < Hh) ? wih2[ocB * Hh + k] : whh2[ocB * Hh + (k - Hh)];
            h[j]     = __float2half_rn(vA);
            h[4 + j] = __float2half_rn(vB);
        }
        *((uint4*)g_wb2 + idx) = *(const uint4*)h;
    }
    if (kt < K1T) {
        __align__(16) __half h[8];
        #pragma unroll
        for (int j = 0; j < 4; ++j) {
            int k = ks[j];
            float vA = (k < Ff) ? wih1[ocA * Ff + k] : whh1[ocA * Hh + (k - Ff)];
            float vB = (k < Ff) ? wih1[ocB * Ff + k] : whh1[ocB * Hh + (k - Ff)];
            h[j]     = __float2half_rn(vA);
            h[4 + j] = __float2half_rn(vB);
        }
        *((uint4*)g_wb1 + idx) = *(const uint4*)h;
    }
    if (idx < G4) {
        int P = idx;
        int rb = P >> 9, wb = (P >> 5) & 15, n = P & 31;
        int oc = (n & 3) * 256 + rb * 128 + wb * 8 + (n >> 2);
        g_b1p[P] = bih1[oc] + bhh1[oc];
        g_b2p[P] = bih2[oc] + bhh2[oc];
    }
}

// ---------------------------------------------------------------------------
// Fused 2-layer LSTM; 2-CTA cluster splits gate cols; h exchanged via one
// bulk DSMEM read per layer per step.
// ---------------------------------------------------------------------------
__global__ void __cluster_dims__(CLU, 1, 1) __launch_bounds__(NT, 1)
lstm_kernel(const float* __restrict__ x,
            const float* __restrict__ wlin, const float* __restrict__ blin,
            float* __restrict__ out) {
    __shared__ __align__(16) __half buf[MB * HST];   // full [x|h1|h2] per CTA

    const int tid  = threadIdx.x;
    const int lane = tid & 31;
    const int w    = tid >> 5;
    const int m    = lane & 3;
    const int g    = lane >> 2;
    const bool modd = (m & 1);
    unsigned rank; asm("mov.u32 %0, %%cluster_ctarank;" : "=r"(rank));
    const unsigned prank = rank ^ 1u;
    const int b0   = (blockIdx.x >> 1) * MB;        // cluster id * 16

    for (int i = tid; i < MB * HST; i += NT) buf[i] = __ushort_as_half(0);

    float c1[4], c2[4];
    #pragma unroll
    for (int j = 0; j < 4; ++j) { c1[j] = 0.f; c2[j] = 0.f; }

    const unsigned sbase = s2u(buf);
    const int lr  = (lane & 7) + 8 * ((lane >> 3) & 1);
    const int lc8 = (lane >> 4) * 8;
    const unsigned aBase = sbase + (unsigned)(lr * HST + lc8) * 2u;

    const uint4* wb1 = (const uint4*)g_wb1 + (rank * 16 + w) * 64 + lane;  // + kt*2048 (+32 for p=1)
    const uint4* wb2 = (const uint4*)g_wb2 + (rank * 16 + w) * 64 + lane;
    const int PB = (int)rank * 512 + w * 32;        // packed bias base

    // update identity: row = g / g+8; unit = rank*128 + w*8 + 2nt + (m>>1)
    const int urow = modd ? (g + 8) : g;
    const unsigned h1addr = sbase + (unsigned)(urow * HST + H1OFF + rank * 128 + w * 8 + (m >> 1)) * 2u;
    const unsigned h2addr = sbase + (unsigned)(urow * HST + H2OFF + rank * 128 + w * 8 + (m >> 1)) * 2u;

    // peer-copy addressing: thread -> one b64 (4 halves) of the peer's half
    const int crow = tid >> 5, cc = tid & 31;
    const unsigned cp1_loc = sbase + (unsigned)(crow * HST + H1OFF + (int)prank * 128 + cc * 4) * 2u;
    const unsigned cp2_loc = sbase + (unsigned)(crow * HST + H2OFF + (int)prank * 128 + cc * 4) * 2u;
    unsigned cp1_rem, cp2_rem;
    asm("mapa.shared::cluster.u32 %0, %1, %2;" : "=r"(cp1_rem) : "r"(cp1_loc), "r"(prank));
    asm("mapa.shared::cluster.u32 %0, %1, %2;" : "=r"(cp2_rem) : "r"(cp2_loc), "r"(prank));

    // stage x(0)
    if (tid < MB * Ff) {
        int b = tid >> 4, f = tid & 15;
        buf[b * HST + f] = __float2half_rn(__ldg(&x[((size_t)(b0 + b) * Tt) * Ff + f]));
    }
    __syncthreads();

    float acc[4][4];

    for (int t = 0; t < Tt; ++t) {
        // ================= LAYER 1 gates (this CTA's 512 cols) =================
        #pragma unroll
        for (int nt = 0; nt < 4; ++nt) {
            float2 bv = __ldg((const float2*)&g_b1p[PB + 8 * nt + 2 * m]);
            acc[nt][0] = bv.x; acc[nt][1] = bv.y; acc[nt][2] = bv.x; acc[nt][3] = bv.y;
        }
        for (int kt = 0; kt < K1T; ++kt) {
            uint4 bv0 = __ldg(wb1 + kt * 2048);
            uint4 bv1 = __ldg(wb1 + kt * 2048 + 32);
            unsigned a0, a1, a2, a3;
            ldsm4(a0, a1, a2, a3, aBase + (unsigned)(kt * 16) * 2u);
            mma16816(acc[0][0], acc[0][1], acc[0][2], acc[0][3], a0, a1, a2, a3, bv0.x, bv0.y);
            mma16816(acc[1][0], acc[1][1], acc[1][2], acc[1][3], a0, a1, a2, a3, bv0.z, bv0.w);
            mma16816(acc[2][0], acc[2][1], acc[2][2], acc[2][3], a0, a1, a2, a3, bv1.x, bv1.y);
            mma16816(acc[3][0], acc[3][1], acc[3][2], acc[3][3], a0, a1, a2, a3, bv1.z, bv1.w);
        }
        __syncthreads();   // all reads of x/h1(old) done

        // ---- update 1: write OWN h1 half locally ----
        #pragma unroll
        for (int nt = 0; nt < 4; ++nt) {
            float t0 = __shfl_xor_sync(0xffffffffu, acc[nt][0], 1);
            float t1 = __shfl_xor_sync(0xffffffffu, acc[nt][1], 1);
            float t2 = __shfl_xor_sync(0xffffffffu, acc[nt][2], 1);
            float t3 = __shfl_xor_sync(0xffffffffu, acc[nt][3], 1);
            float zi = modd ? t2 : acc[nt][0];
            float zf = modd ? t3 : acc[nt][1];
            float zg = modd ? acc[nt][2] : t0;
            float zo = modd ? acc[nt][3] : t1;
            c1[nt] = sigf(zf) * c1[nt] + sigf(zi) * tanhg(zg);
            float h = sigf(zo) * tanhg(c1[nt]);
            sts16(h1addr + 4u * nt, __float2half_rn(h));
        }
        cluster_sync_all();   // own halves visible cluster-wide

        // ---- bulk-copy peer h1 half (one b64 per thread) ----
        {
            unsigned long long v;
            asm volatile("ld.shared::cluster.b64 %0, [%1];" : "=l"(v) : "r"(cp1_rem));
            asm volatile("st.shared.b64 [%0], %1;" :: "r"(cp1_loc), "l"(v) : "memory");
        }
        __syncthreads();      // full h1(new) local

        // ================= LAYER 2 gates =================
        #pragma unroll
        for (int nt = 0; nt < 4; ++nt) {
            float2 bv = __ldg((const float2*)&g_b2p[PB + 8 * nt + 2 * m]);
            acc[nt][0] = bv.x; acc[nt][1] = bv.y; acc[nt][2] = bv.x; acc[nt][3] = bv.y;
        }
        for (int kt = 0; kt < K2T; ++kt) {
            uint4 bv0 = __ldg(wb2 + kt * 2048);
            uint4 bv1 = __ldg(wb2 + kt * 2048 + 32);
            unsigned a0, a1, a2, a3;
            ldsm4(a0, a1, a2, a3, aBase + (unsigned)(H1OFF + kt * 16) * 2u);
            mma16816(acc[0][0], acc[0][1], acc[0][2], acc[0][3], a0, a1, a2, a3, bv0.x, bv0.y);
            mma16816(acc[1][0], acc[1][1], acc[1][2], acc[1][3], a0, a1, a2, a3, bv0.z, bv0.w);
            mma16816(acc[2][0], acc[2][1], acc[2][2], acc[2][3], a0, a1, a2, a3, bv1.x, bv1.y);
            mma16816(acc[3][0], acc[3][1], acc[3][2], acc[3][3], a0, a1, a2, a3, bv1.z, bv1.w);
        }
        __syncthreads();   // all reads of h1(new)/h2(old) done

        // ---- update 2: write OWN h2 half + stage x(t+1) ----
        #pragma unroll
        for (int nt = 0; nt < 4; ++nt) {
            float t0 = __shfl_xor_sync(0xffffffffu, acc[nt][0], 1);
            float t1 = __shfl_xor_sync(0xffffffffu, acc[nt][1], 1);
            float t2 = __shfl_xor_sync(0xffffffffu, acc[nt][2], 1);
            float t3 = __shfl_xor_sync(0xffffffffu, acc[nt][3], 1);
            float zi = modd ? t2 : acc[nt][0];
            float zf = modd ? t3 : acc[nt][1];
            float zg = modd ? acc[nt][2] : t0;
            float zo = modd ? acc[nt][3] : t1;
            c2[nt] = sigf(zf) * c2[nt] + sigf(zi) * tanhg(zg);
            float h = sigf(zo) * tanhg(c2[nt]);
            sts16(h2addr + 4u * nt, __float2half_rn(h));
        }
        if (tid < MB * Ff && t + 1 < Tt) {
            int b = tid >> 4, f = tid & 15;
            buf[b * HST + f] =
                __float2half_rn(__ldg(&x[((size_t)(b0 + b) * Tt + (t + 1)) * Ff + f]));
        }
        cluster_sync_all();   // own h2 halves visible cluster-wide

        // ---- bulk-copy peer h2 half ----
        {
            unsigned long long v;
            asm volatile("ld.shared::cluster.b64 %0, [%1];" : "=l"(v) : "r"(cp2_rem));
            asm volatile("st.shared.b64 [%0], %1;" :: "r"(cp2_loc), "l"(v) : "memory");
        }
        __syncthreads();      // full h2(new) + x(t+1) local
    }

    // ================= linear head: rank 0, warp w -> batch row w =================
    if (rank == 0 && w < MB) {
        float s = 0.f;
        #pragma unroll
        for (int u = lane; u < Hh; u += 32)
            s += __half2float(buf[w * HST + H2OFF + u]) * __ldg(&wlin[u]);
        #pragma unroll
        for (int off = 16; off; off >>= 1) s += __shfl_xor_sync(0xffffffffu, s, off);
        if (lane == 0) out[b0 + w] = s + blin[0];
    }
}

// ---------------------------------------------------------------------------
extern "C" void kernel_launch(void* const* d_in, const int* in_sizes, int n_in,
                              void* d_out, int out_size) {
    const float* x    = (const float*)d_in[0];
    const float* wih1 = (const float*)d_in[1];
    const float* whh1 = (const float*)d_in[2];
    const float* bih1 = (const float*)d_in[3];
    const float* bhh1 = (const float*)d_in[4];
    const float* wih2 = (const float*)d_in[5];
    const float* whh2 = (const float*)d_in[6];
    const float* bih2 = (const float*)d_in[7];
    const float* bhh2 = (const float*)d_in[8];
    const float* wlin = (const float*)d_in[9];
    const float* blin = (const float*)d_in[10];
    float* out = (float*)d_out;

    prep_kernel<<<(K2T * 2048 + 255) / 256, 256>>>(wih1, whh1, bih1, bhh1,
                                                   wih2, whh2, bih2, bhh2);
    lstm_kernel<<<NCg, NT>>>(x, wlin, blin, out);
}

// round 15
// speedup vs baseline: 2.3032x; 1.3489x over previous
#include <cuda_runtime.h>
#include <cuda_fp16.h>

#define Bq   512
#define Tt   365
#define Ff   16
#define Hh   256
#define G4   1024
#define CLU  4       // CTAs per cluster (gate-col split)
#define NCg  128     // CTAs total (32 clusters x 4)
#define MB   16      // batch rows per cluster
#define NT   512     // 16 warps; warp owns 16 packed cols (2 n8-tiles)
#define K1T  17      // layer-1 k-tiles (272 = 16 x + 256 h1)
#define K2T  32      // layer-2 k-tiles (512 = 256 h1 + 256 h2)
#define HST  536     // buffer col stride (halves): [x 16 | h1 256 | h2 256 | pad]
#define H1OFF 16
#define H2OFF 272

// ---------------------------------------------------------------------------
// fp16 B fragments (m16n8k16 .col), gate-interleaved, 4-way CLUSTER-SPLIT:
//   packed col P = r*256 + w*16 + n ; gate = n&3, unit = r*64 + w*4 + (n>>2)
//   frag uint4 idx = kt*2048 + (r*16 + w)*32 + lane
//   uint4 halves 0..3 = tile 0 (col w16+c), 4..7 = tile 1 (col w16+8+c); rows 2m,2m+1,2m+8,2m+9
// ---------------------------------------------------------------------------
__device__ __align__(16) __half g_wb1[(Ff + Hh) * G4];
__device__ __align__(16) __half g_wb2[2 * Hh * G4];
__device__ float g_b1p[G4];
__device__ float g_b2p[G4];

__device__ __forceinline__ float sigf(float x) {
    return __fdividef(1.0f, 1.0f + __expf(-x));
}
__device__ __forceinline__ float tanhg(float x) {
    return __fdividef(2.0f, 1.0f + __expf(-2.0f * x)) - 1.0f;
}
__device__ __forceinline__ unsigned s2u(const void* p) {
    unsigned a;
    asm("{ .reg .u64 t; cvta.to.shared.u64 t, %1; cvt.u32.u64 %0, t; }" : "=r"(a) : "l"(p));
    return a;
}
__device__ __forceinline__ void ldsm4(unsigned& a0, unsigned& a1, unsigned& a2, unsigned& a3,
                                      unsigned addr) {
    asm volatile("ldmatrix.sync.aligned.m8n8.x4.shared.b16 {%0,%1,%2,%3}, [%4];"
                 : "=r"(a0), "=r"(a1), "=r"(a2), "=r"(a3) : "r"(addr));
}
__device__ __forceinline__ void mma16816(float& d0, float& d1, float& d2, float& d3,
                                         unsigned a0, unsigned a1, unsigned a2, unsigned a3,
                                         unsigned b0, unsigned b1) {
    asm volatile("mma.sync.aligned.m16n8k16.row.col.f32.f16.f16.f32 "
                 "{%0,%1,%2,%3}, {%4,%5,%6,%7}, {%8,%9}, {%0,%1,%2,%3};"
                 : "+f"(d0), "+f"(d1), "+f"(d2), "+f"(d3)
                 : "r"(a0), "r"(a1), "r"(a2), "r"(a3), "r"(b0), "r"(b1));
}
__device__ __forceinline__ void sts16(unsigned addr, __half v) {
    asm volatile("st.shared.b16 [%0], %1;" :: "r"(addr), "h"(__half_as_ushort(v)) : "memory");
}
__device__ __forceinline__ void cluster_sync_all() {
    asm volatile("barrier.cluster.arrive.aligned;" ::: "memory");
    asm volatile("barrier.cluster.wait.aligned;"   ::: "memory");
}

// ---------------------------------------------------------------------------
// Prep: pack B fragments (4-way split cols) + packed biases.
// ---------------------------------------------------------------------------
__global__ void prep_kernel(const float* __restrict__ wih1, const float* __restrict__ whh1,
                            const float* __restrict__ bih1, const float* __restrict__ bhh1,
                            const float* __restrict__ wih2, const float* __restrict__ whh2,
                            const float* __restrict__ bih2, const float* __restrict__ bhh2) {
    int idx = blockIdx.x * blockDim.x + threadIdx.x;   // uint4 index, over K2T*2048 = 65536
    int lane = idx & 31, w = (idx >> 5) & 15, r = (idx >> 9) & 3, kt = idx >> 11;
    int m = lane & 3, c = lane >> 2;
    int k0 = kt * 16;
    int nA = c, nB = 8 + c;                            // packed cols within warp's 16
    int ocA = (nA & 3) * 256 + r * 64 + w * 4 + (nA >> 2);
    int ocB = (nB & 3) * 256 + r * 64 + w * 4 + (nB >> 2);
    int ks[4] = {k0 + 2 * m, k0 + 2 * m + 1, k0 + 2 * m + 8, k0 + 2 * m + 9};

    if (kt < K2T) {
        __align__(16) __half h[8];
        #pragma unroll
        for (int j = 0; j < 4; ++j) {
            int k = ks[j];
            float vA = (k < Hh) ? wih2[ocA * Hh + k] : whh2[ocA * Hh + (k - Hh)];
            float vB = (k < Hh) ? wih2[ocB * Hh + k] : whh2[ocB * Hh + (k - Hh)];
            h[j]     = __float2half_rn(vA);
            h[4 + j] = __float2half_rn(vB);
        }
        *((uint4*)g_wb2 + idx) = *(const uint4*)h;
    }
    if (kt < K1T) {
        __align__(16) __half h[8];
        #pragma unroll
        for (int j = 0; j < 4; ++j) {
            int k = ks[j];
            float vA = (k < Ff) ? wih1[ocA * Ff + k] : whh1[ocA * Hh + (k - Ff)];
            float vB = (k < Ff) ? wih1[ocB * Ff + k] : whh1[ocB * Hh + (k - Ff)];
            h[j]     = __float2half_rn(vA);
            h[4 + j] = __float2half_rn(vB);
        }
        *((uint4*)g_wb1 + idx) = *(const uint4*)h;
    }
    if (idx < G4) {
        int P = idx;
        int rb = P >> 8, wb = (P >> 4) & 15, n = P & 15;
        int oc = (n & 3) * 256 + rb * 64 + wb * 4 + (n >> 2);
        g_b1p[P] = bih1[oc] + bhh1[oc];
        g_b2p[P] = bih2[oc] + bhh2[oc];
    }
}

// ---------------------------------------------------------------------------
// Fused 2-layer LSTM; 4-CTA cluster splits gate cols 4-way; h quarters
// exchanged via 3 x b32 DSMEM reads per thread per layer.
// ---------------------------------------------------------------------------
__global__ void __cluster_dims__(CLU, 1, 1) __launch_bounds__(NT, 1)
lstm_kernel(const float* __restrict__ x,
            const float* __restrict__ wlin, const float* __restrict__ blin,
            float* __restrict__ out) {
    __shared__ __align__(16) __half buf[MB * HST];   // full [x|h1|h2] per CTA

    const int tid  = threadIdx.x;
    const int lane = tid & 31;
    const int w    = tid >> 5;
    const int m    = lane & 3;
    const int g    = lane >> 2;
    const bool modd = (m & 1);
    unsigned rank; asm("mov.u32 %0, %%cluster_ctarank;" : "=r"(rank));
    const int b0   = (blockIdx.x >> 2) * MB;        // cluster id * 16

    for (int i = tid; i < MB * HST; i += NT) buf[i] = __ushort_as_half(0);

    float c1[2] = {0.f, 0.f};
    float c2[2] = {0.f, 0.f};

    const unsigned sbase = s2u(buf);
    const int lr  = (lane & 7) + 8 * ((lane >> 3) & 1);
    const int lc8 = (lane >> 4) * 8;
    const unsigned aBase = sbase + (unsigned)(lr * HST + lc8) * 2u;

    const uint4* wb1 = (const uint4*)g_wb1 + ((int)rank * 16 + w) * 32 + lane; // + kt*2048
    const uint4* wb2 = (const uint4*)g_wb2 + ((int)rank * 16 + w) * 32 + lane;
    const int PB = (int)rank * 256 + w * 16;        // packed bias base

    // update identity: row = g / g+8; unit = rank*64 + w*4 + 2nt + (m>>1)
    const int urow = modd ? (g + 8) : g;
    const unsigned h1addr = sbase + (unsigned)(urow * HST + H1OFF + (int)rank * 64 + w * 4 + (m >> 1)) * 2u;
    const unsigned h2addr = sbase + (unsigned)(urow * HST + H2OFF + (int)rank * 64 + w * 4 + (m >> 1)) * 2u;

    // peer-copy addressing: thread -> one b32 (2 halves) per peer quarter
    const int crow = tid >> 5, cc = tid & 31;
    unsigned cp1_loc[3], cp1_rem[3], cp2_loc[3], cp2_rem[3];
    #pragma unroll
    for (int pp = 1; pp <= 3; ++pp) {
        unsigned pr = rank ^ (unsigned)pp;
        unsigned l1 = sbase + (unsigned)(crow * HST + H1OFF + (int)pr * 64 + cc * 2) * 2u;
        unsigned l2 = sbase + (unsigned)(crow * HST + H2OFF + (int)pr * 64 + cc * 2) * 2u;
        cp1_loc[pp - 1] = l1;  cp2_loc[pp - 1] = l2;
        asm("mapa.shared::cluster.u32 %0, %1, %2;" : "=r"(cp1_rem[pp - 1]) : "r"(l1), "r"(pr));
        asm("mapa.shared::cluster.u32 %0, %1, %2;" : "=r"(cp2_rem[pp - 1]) : "r"(l2), "r"(pr));
    }

    // stage x(0)
    if (tid < MB * Ff) {
        int b = tid >> 4, f = tid & 15;
        buf[b * HST + f] = __float2half_rn(__ldg(&x[((size_t)(b0 + b) * Tt) * Ff + f]));
    }
    __syncthreads();

    float acc[2][4];

    for (int t = 0; t < Tt; ++t) {
        // ================= LAYER 1 gates (this CTA's 256 cols) =================
        #pragma unroll
        for (int nt = 0; nt < 2; ++nt) {
            float2 bv = __ldg((const float2*)&g_b1p[PB + 8 * nt + 2 * m]);
            acc[nt][0] = bv.x; acc[nt][1] = bv.y; acc[nt][2] = bv.x; acc[nt][3] = bv.y;
        }
        for (int kt = 0; kt < K1T; ++kt) {
            uint4 bv0 = __ldg(wb1 + kt * 2048);
            unsigned a0, a1, a2, a3;
            ldsm4(a0, a1, a2, a3, aBase + (unsigned)(kt * 16) * 2u);
            mma16816(acc[0][0], acc[0][1], acc[0][2], acc[0][3], a0, a1, a2, a3, bv0.x, bv0.y);
            mma16816(acc[1][0], acc[1][1], acc[1][2], acc[1][3], a0, a1, a2, a3, bv0.z, bv0.w);
        }
        __syncthreads();   // all reads of x/h1(old) done

        // ---- update 1: write OWN h1 quarter locally ----
        #pragma unroll
        for (int nt = 0; nt < 2; ++nt) {
            float t0 = __shfl_xor_sync(0xffffffffu, acc[nt][0], 1);
            float t1 = __shfl_xor_sync(0xffffffffu, acc[nt][1], 1);
            float t2 = __shfl_xor_sync(0xffffffffu, acc[nt][2], 1);
            float t3 = __shfl_xor_sync(0xffffffffu, acc[nt][3], 1);
            float zi = modd ? t2 : acc[nt][0];
            float zf = modd ? t3 : acc[nt][1];
            float zg = modd ? acc[nt][2] : t0;
            float zo = modd ? acc[nt][3] : t1;
            c1[nt] = sigf(zf) * c1[nt] + sigf(zi) * tanhg(zg);
            float h = sigf(zo) * tanhg(c1[nt]);
            sts16(h1addr + 4u * nt, __float2half_rn(h));
        }
        cluster_sync_all();   // own quarters visible cluster-wide

        // ---- copy 3 peer h1 quarters (one b32 per peer per thread) ----
        #pragma unroll
        for (int pp = 0; pp < 3; ++pp) {
            unsigned v;
            asm volatile("ld.shared::cluster.b32 %0, [%1];" : "=r"(v) : "r"(cp1_rem[pp]));
            asm volatile("st.shared.b32 [%0], %1;" :: "r"(cp1_loc[pp]), "r"(v) : "memory");
        }
        __syncthreads();      // full h1(new) local

        // ================= LAYER 2 gates =================
        #pragma unroll
        for (int nt = 0; nt < 2; ++nt) {
            float2 bv = __ldg((const float2*)&g_b2p[PB + 8 * nt + 2 * m]);
            acc[nt][0] = bv.x; acc[nt][1] = bv.y; acc[nt][2] = bv.x; acc[nt][3] = bv.y;
        }
        for (int kt = 0; kt < K2T; ++kt) {
            uint4 bv0 = __ldg(wb2 + kt * 2048);
            unsigned a0, a1, a2, a3;
            ldsm4(a0, a1, a2, a3, aBase + (unsigned)(H1OFF + kt * 16) * 2u);
            mma16816(acc[0][0], acc[0][1], acc[0][2], acc[0][3], a0, a1, a2, a3, bv0.x, bv0.y);
            mma16816(acc[1][0], acc[1][1], acc[1][2], acc[1][3], a0, a1, a2, a3, bv0.z, bv0.w);
        }
        __syncthreads();   // all reads of h1(new)/h2(old) done

        // ---- update 2: write OWN h2 quarter + stage x(t+1) ----
        #pragma unroll
        for (int nt = 0; nt < 2; ++nt) {
            float t0 = __shfl_xor_sync(0xffffffffu, acc[nt][0], 1);
            float t1 = __shfl_xor_sync(0xffffffffu, acc[nt][1], 1);
            float t2 = __shfl_xor_sync(0xffffffffu, acc[nt][2], 1);
            float t3 = __shfl_xor_sync(0xffffffffu, acc[nt][3], 1);
            float zi = modd ? t2 : acc[nt][0];
            float zf = modd ? t3 : acc[nt][1];
            float zg = modd ? acc[nt][2] : t0;
            float zo = modd ? acc[nt][3] : t1;
            c2[nt] = sigf(zf) * c2[nt] + sigf(zi) * tanhg(zg);
            float h = sigf(zo) * tanhg(c2[nt]);
            sts16(h2addr + 4u * nt, __float2half_rn(h));
        }
        if (tid < MB * Ff && t + 1 < Tt) {
            int b = tid >> 4, f = tid & 15;
            buf[b * HST + f] =
                __float2half_rn(__ldg(&x[((size_t)(b0 + b) * Tt + (t + 1)) * Ff + f]));
        }
        cluster_sync_all();   // own h2 quarters visible cluster-wide

        // ---- copy 3 peer h2 quarters ----
        #pragma unroll
        for (int pp = 0; pp < 3; ++pp) {
            unsigned v;
            asm volatile("ld.shared::cluster.b32 %0, [%1];" : "=r"(v) : "r"(cp2_rem[pp]));
            asm volatile("st.shared.b32 [%0], %1;" :: "r"(cp2_loc[pp]), "r"(v) : "memory");
        }
        __syncthreads();      // full h2(new) + x(t+1) local
    }

    // ================= linear head: rank 0, warp w -> batch row w =================
    if (rank == 0 && w < MB) {
        float s = 0.f;
        #pragma unroll
        for (int u = lane; u < Hh; u += 32)
            s += __half2float(buf[w * HST + H2OFF + u]) * __ldg(&wlin[u]);
        #pragma unroll
        for (int off = 16; off; off >>= 1) s += __shfl_xor_sync(0xffffffffu, s, off);
        if (lane == 0) out[b0 + w] = s + blin[0];
    }
}

// ---------------------------------------------------------------------------
extern "C" void kernel_launch(void* const* d_in, const int* in_sizes, int n_in,
                              void* d_out, int out_size) {
    const float* x    = (const float*)d_in[0];
    const float* wih1 = (const float*)d_in[1];
    const float* whh1 = (const float*)d_in[2];
    const float* bih1 = (const float*)d_in[3];
    const float* bhh1 = (const float*)d_in[4];
    const float* wih2 = (const float*)d_in[5];
    const float* whh2 = (const float*)d_in[6];
    const float* bih2 = (const float*)d_in[7];
    const float* bhh2 = (const float*)d_in[8];
    const float* wlin = (const float*)d_in[9];
    const float* blin = (const float*)d_in[10];
    float* out = (float*)d_out;

    prep_kernel<<<(K2T * 2048 + 255) / 256, 256>>>(wih1, whh1, bih1, bhh1,
                                                   wih2, whh2, bih2, bhh2);
    lstm_kernel<<<NCg, NT>>>(x, wlin, blin, out);
}

// round 16
// speedup vs baseline: 2.5233x; 1.0955x over previous
#include <cuda_runtime.h>
#include <cuda_fp16.h>

#define Bq   512
#define Tt   365
#define Ff   16
#define Hh   256
#define G4   1024
#define CLU  4       // CTAs per cluster (gate-col split)
#define NCg  128     // CTAs total (32 clusters x 4)
#define MB   16      // batch rows per cluster
#define NT   512     // 16 warps; warp owns 16 packed cols (2 n8-tiles)
#define K1T  17      // layer-1 k-tiles (272 = 16 x + 256 h1)
#define HST  536     // buffer col stride (halves): [x 16 | h1 256 | h2 256 | pad]
#define H1OFF 16
#define H2OFF 272

// ---------------------------------------------------------------------------
// fp16 B fragments (m16n8k16 .col), gate-interleaved, 4-way CLUSTER-SPLIT:
//   packed col P = r*256 + w*16 + n ; gate = n&3, unit = r*64 + w*4 + (n>>2)
//   frag uint4 idx = kt*2048 + (r*16 + w)*32 + lane
// ---------------------------------------------------------------------------
__device__ __align__(16) __half g_wb1[(Ff + Hh) * G4];
__device__ __align__(16) __half g_wb2[2 * Hh * G4];
__device__ float g_b1p[G4];
__device__ float g_b2p[G4];

__device__ __forceinline__ float sigf(float x) {
    return __fdividef(1.0f, 1.0f + __expf(-x));
}
__device__ __forceinline__ float tanhg(float x) {
    return __fdividef(2.0f, 1.0f + __expf(-2.0f * x)) - 1.0f;
}
__device__ __forceinline__ unsigned s2u(const void* p) {
    unsigned a;
    asm("{ .reg .u64 t; cvta.to.shared.u64 t, %1; cvt.u32.u64 %0, t; }" : "=r"(a) : "l"(p));
    return a;
}
__device__ __forceinline__ void ldsm4(unsigned& a0, unsigned& a1, unsigned& a2, unsigned& a3,
                                      unsigned addr) {
    asm volatile("ldmatrix.sync.aligned.m8n8.x4.shared.b16 {%0,%1,%2,%3}, [%4];"
                 : "=r"(a0), "=r"(a1), "=r"(a2), "=r"(a3) : "r"(addr));
}
__device__ __forceinline__ void mma16816(float& d0, float& d1, float& d2, float& d3,
                                         unsigned a0, unsigned a1, unsigned a2, unsigned a3,
                                         unsigned b0, unsigned b1) {
    asm volatile("mma.sync.aligned.m16n8k16.row.col.f32.f16.f16.f32 "
                 "{%0,%1,%2,%3}, {%4,%5,%6,%7}, {%8,%9}, {%0,%1,%2,%3};"
                 : "+f"(d0), "+f"(d1), "+f"(d2), "+f"(d3)
                 : "r"(a0), "r"(a1), "r"(a2), "r"(a3), "r"(b0), "r"(b1));
}
__device__ __forceinline__ void sts16(unsigned addr, __half v) {
    asm volatile("st.shared.b16 [%0], %1;" :: "r"(addr), "h"(__half_as_ushort(v)) : "memory");
}
#define CL_ARRIVE() asm volatile("barrier.cluster.arrive.aligned;" ::: "memory")
#define CL_WAIT()   asm volatile("barrier.cluster.wait.aligned;"   ::: "memory")

// ---------------------------------------------------------------------------
// Prep: pack B fragments (4-way split cols) + packed biases. (unchanged)
// ---------------------------------------------------------------------------
__global__ void prep_kernel(const float* __restrict__ wih1, const float* __restrict__ whh1,
                            const float* __restrict__ bih1, const float* __restrict__ bhh1,
                            const float* __restrict__ wih2, const float* __restrict__ whh2,
                            const float* __restrict__ bih2, const float* __restrict__ bhh2) {
    int idx = blockIdx.x * blockDim.x + threadIdx.x;   // uint4 index, over 32*2048 = 65536
    int lane = idx & 31, w = (idx >> 5) & 15, r = (idx >> 9) & 3, kt = idx >> 11;
    int m = lane & 3, c = lane >> 2;
    int k0 = kt * 16;
    int nA = c, nB = 8 + c;
    int ocA = (nA & 3) * 256 + r * 64 + w * 4 + (nA >> 2);
    int ocB = (nB & 3) * 256 + r * 64 + w * 4 + (nB >> 2);
    int ks[4] = {k0 + 2 * m, k0 + 2 * m + 1, k0 + 2 * m + 8, k0 + 2 * m + 9};

    if (kt < 32) {
        __align__(16) __half h[8];
        #pragma unroll
        for (int j = 0; j < 4; ++j) {
            int k = ks[j];
            float vA = (k < Hh) ? wih2[ocA * Hh + k] : whh2[ocA * Hh + (k - Hh)];
            float vB = (k < Hh) ? wih2[ocB * Hh + k] : whh2[ocB * Hh + (k - Hh)];
            h[j]     = __float2half_rn(vA);
            h[4 + j] = __float2half_rn(vB);
        }
        *((uint4*)g_wb2 + idx) = *(const uint4*)h;
    }
    if (kt < K1T) {
        __align__(16) __half h[8];
        #pragma unroll
        for (int j = 0; j < 4; ++j) {
            int k = ks[j];
            float vA = (k < Ff) ? wih1[ocA * Ff + k] : whh1[ocA * Hh + (k - Ff)];
            float vB = (k < Ff) ? wih1[ocB * Ff + k] : whh1[ocB * Hh + (k - Ff)];
            h[j]     = __float2half_rn(vA);
            h[4 + j] = __float2half_rn(vB);
        }
        *((uint4*)g_wb1 + idx) = *(const uint4*)h;
    }
    if (idx < G4) {
        int P = idx;
        int rb = P >> 8, wb = (P >> 4) & 15, n = P & 15;
        int oc = (n & 3) * 256 + rb * 64 + wb * 4 + (n >> 2);
        g_b1p[P] = bih1[oc] + bhh1[oc];
        g_b2p[P] = bih2[oc] + bhh2[oc];
    }
}

// ---------------------------------------------------------------------------
// Fused 2-layer LSTM; 4-way cluster split; split-phase barriers with the
// waits hidden under independent MMA blocks (L2 h2-tiles / L1 gates).
// ---------------------------------------------------------------------------
__global__ void __cluster_dims__(CLU, 1, 1) __launch_bounds__(NT, 1)
lstm_kernel(const float* __restrict__ x,
            const float* __restrict__ wlin, const float* __restrict__ blin,
            float* __restrict__ out) {
    __shared__ __align__(16) __half buf[MB * HST];

    const int tid  = threadIdx.x;
    const int lane = tid & 31;
    const int w    = tid >> 5;
    const int m    = lane & 3;
    const int g    = lane >> 2;
    const bool modd = (m & 1);
    unsigned rank; asm("mov.u32 %0, %%cluster_ctarank;" : "=r"(rank));
    const int b0   = (blockIdx.x >> 2) * MB;

    for (int i = tid; i < MB * HST; i += NT) buf[i] = __ushort_as_half(0);

    float c1[2] = {0.f, 0.f};
    float c2[2] = {0.f, 0.f};

    const unsigned sbase = s2u(buf);
    const int lr  = (lane & 7) + 8 * ((lane >> 3) & 1);
    const int lc8 = (lane >> 4) * 8;
    const unsigned aBase = sbase + (unsigned)(lr * HST + lc8) * 2u;

    const uint4* wb1 = (const uint4*)g_wb1 + ((int)rank * 16 + w) * 32 + lane;
    const uint4* wb2 = (const uint4*)g_wb2 + ((int)rank * 16 + w) * 32 + lane;
    const int PB = (int)rank * 256 + w * 16;

    // hoisted biases
    float2 b1v[2], b2v[2];
    #pragma unroll
    for (int nt = 0; nt < 2; ++nt) {
        b1v[nt] = *(const float2*)&g_b1p[PB + 8 * nt + 2 * m];
        b2v[nt] = *(const float2*)&g_b2p[PB + 8 * nt + 2 * m];
    }

    const int urow = modd ? (g + 8) : g;
    const unsigned h1addr = sbase + (unsigned)(urow * HST + H1OFF + (int)rank * 64 + w * 4 + (m >> 1)) * 2u;
    const unsigned h2addr = sbase + (unsigned)(urow * HST + H2OFF + (int)rank * 64 + w * 4 + (m >> 1)) * 2u;

    // peer-copy addressing: one b32 per peer per thread
    const int crow = tid >> 5, cc = tid & 31;
    unsigned cp1_loc[3], cp1_rem[3], cp2_loc[3], cp2_rem[3];
    #pragma unroll
    for (int pp = 1; pp <= 3; ++pp) {
        unsigned pr = rank ^ (unsigned)pp;
        unsigned l1 = sbase + (unsigned)(crow * HST + H1OFF + (int)pr * 64 + cc * 2) * 2u;
        unsigned l2 = sbase + (unsigned)(crow * HST + H2OFF + (int)pr * 64 + cc * 2) * 2u;
        cp1_loc[pp - 1] = l1;  cp2_loc[pp - 1] = l2;
        asm("mapa.shared::cluster.u32 %0, %1, %2;" : "=r"(cp1_rem[pp - 1]) : "r"(l1), "r"(pr));
        asm("mapa.shared::cluster.u32 %0, %1, %2;" : "=r"(cp2_rem[pp - 1]) : "r"(l2), "r"(pr));
    }

    // stage x(0)
    if (tid < MB * Ff) {
        int b = tid >> 4, f = tid & 15;
        buf[b * HST + f] = __float2half_rn(__ldg(&x[((size_t)(b0 + b) * Tt) * Ff + f]));
    }
    __syncthreads();

    // init sync (zeros visible) + prime the first in-loop WAIT
    CL_ARRIVE(); CL_WAIT();
    CL_ARRIVE();

    float acc[2][4];

    for (int t = 0; t < Tt; ++t) {
        // ===== LAYER 1 gates (x + full h1(t-1); all local) =====
        #pragma unroll
        for (int nt = 0; nt < 2; ++nt) {
            acc[nt][0] = b1v[nt].x; acc[nt][1] = b1v[nt].y;
            acc[nt][2] = b1v[nt].x; acc[nt][3] = b1v[nt].y;
        }
        for (int kt = 0; kt < K1T; ++kt) {
            uint4 bv0 = __ldg(wb1 + kt * 2048);
            unsigned a0, a1, a2, a3;
            ldsm4(a0, a1, a2, a3, aBase + (unsigned)(kt * 16) * 2u);
            mma16816(acc[0][0], acc[0][1], acc[0][2], acc[0][3], a0, a1, a2, a3, bv0.x, bv0.y);
            mma16816(acc[1][0], acc[1][1], acc[1][2], acc[1][3], a0, a1, a2, a3, bv0.z, bv0.w);
        }

        // ---- WAIT(#2): peers' h2(t-1) quarters published; copy them ----
        CL_WAIT();
        #pragma unroll
        for (int pp = 0; pp < 3; ++pp) {
            unsigned v;
            asm volatile("ld.shared::cluster.b32 %0, [%1];" : "=r"(v) : "r"(cp2_rem[pp]));
            asm volatile("st.shared.b32 [%0], %1;" :: "r"(cp2_loc[pp]), "r"(v) : "memory");
        }
        __syncthreads();   // h2(t-1) full local; also: all gates reads done

        // ---- L1 update: write OWN h1 quarter ----
        #pragma unroll
        for (int nt = 0; nt < 2; ++nt) {
            float t0 = __shfl_xor_sync(0xffffffffu, acc[nt][0], 1);
            float t1 = __shfl_xor_sync(0xffffffffu, acc[nt][1], 1);
            float t2 = __shfl_xor_sync(0xffffffffu, acc[nt][2], 1);
            float t3 = __shfl_xor_sync(0xffffffffu, acc[nt][3], 1);
            float zi = modd ? t2 : acc[nt][0];
            float zf = modd ? t3 : acc[nt][1];
            float zg = modd ? acc[nt][2] : t0;
            float zo = modd ? acc[nt][3] : t1;
            c1[nt] = sigf(zf) * c1[nt] + sigf(zi) * tanhg(zg);
            float h = sigf(zo) * tanhg(c1[nt]);
            sts16(h1addr + 4u * nt, __float2half_rn(h));
        }
        CL_ARRIVE();       // #1: own h1(t) quarter published

        // ===== LAYER 2 gates part A: h2(t-1) tiles (kt 16..31; local) =====
        #pragma unroll
        for (int nt = 0; nt < 2; ++nt) {
            acc[nt][0] = b2v[nt].x; acc[nt][1] = b2v[nt].y;
            acc[nt][2] = b2v[nt].x; acc[nt][3] = b2v[nt].y;
        }
        for (int kt = 16; kt < 32; ++kt) {
            uint4 bv0 = __ldg(wb2 + kt * 2048);
            unsigned a0, a1, a2, a3;
            ldsm4(a0, a1, a2, a3, aBase + (unsigned)(H1OFF + kt * 16) * 2u);
            mma16816(acc[0][0], acc[0][1], acc[0][2], acc[0][3], a0, a1, a2, a3, bv0.x, bv0.y);
            mma16816(acc[1][0], acc[1][1], acc[1][2], acc[1][3], a0, a1, a2, a3, bv0.z, bv0.w);
        }

        // ---- WAIT(#1): peers' h1(t) quarters published; copy them ----
        CL_WAIT();
        #pragma unroll
        for (int pp = 0; pp < 3; ++pp) {
            unsigned v;
            asm volatile("ld.shared::cluster.b32 %0, [%1];" : "=r"(v) : "r"(cp1_rem[pp]));
            asm volatile("st.shared.b32 [%0], %1;" :: "r"(cp1_loc[pp]), "r"(v) : "memory");
        }
        __syncthreads();   // h1(t) full local; all L2A h2 reads done

        // ===== LAYER 2 gates part B: h1(t) tiles (kt 0..15) =====
        for (int kt = 0; kt < 16; ++kt) {
            uint4 bv0 = __ldg(wb2 + kt * 2048);
            unsigned a0, a1, a2, a3;
            ldsm4(a0, a1, a2, a3, aBase + (unsigned)(H1OFF + kt * 16) * 2u);
            mma16816(acc[0][0], acc[0][1], acc[0][2], acc[0][3], a0, a1, a2, a3, bv0.x, bv0.y);
            mma16816(acc[1][0], acc[1][1], acc[1][2], acc[1][3], a0, a1, a2, a3, bv0.z, bv0.w);
        }

        // ---- L2 update: write OWN h2 quarter + stage x(t+1) ----
        #pragma unroll
        for (int nt = 0; nt < 2; ++nt) {
            float t0 = __shfl_xor_sync(0xffffffffu, acc[nt][0], 1);
            float t1 = __shfl_xor_sync(0xffffffffu, acc[nt][1], 1);
            float t2 = __shfl_xor_sync(0xffffffffu, acc[nt][2], 1);
            float t3 = __shfl_xor_sync(0xffffffffu, acc[nt][3], 1);
            float zi = modd ? t2 : acc[nt][0];
            float zf = modd ? t3 : acc[nt][1];
            float zg = modd ? acc[nt][2] : t0;
            float zo = modd ? acc[nt][3] : t1;
            c2[nt] = sigf(zf) * c2[nt] + sigf(zi) * tanhg(zg);
            float h = sigf(zo) * tanhg(c2[nt]);
            sts16(h2addr + 4u * nt, __float2half_rn(h));
        }
        if (tid < MB * Ff && t + 1 < Tt) {
            int b = tid >> 4, f = tid & 15;
            buf[b * HST + f] =
                __float2half_rn(__ldg(&x[((size_t)(b0 + b) * Tt + (t + 1)) * Ff + f]));
        }
        CL_ARRIVE();       // #2: own h2(t) quarter published
        __syncthreads();   // local: x(t+1) + own h2 visible before next L1 gates
    }

    // drain final phase: assemble full h2(T-1)
    CL_WAIT();
    #pragma unroll
    for (int pp = 0; pp < 3; ++pp) {
        unsigned v;
        asm volatile("ld.shared::cluster.b32 %0, [%1];" : "=r"(v) : "r"(cp2_rem[pp]));
        asm volatile("st.shared.b32 [%0], %1;" :: "r"(cp2_loc[pp]), "r"(v) : "memory");
    }
    __syncthreads();

    // ================= linear head: rank 0, warp w -> batch row w =================
    if (rank == 0 && w < MB) {
        float s = 0.f;
        #pragma unroll
        for (int u = lane; u < Hh; u += 32)
            s += __half2float(buf[w * HST + H2OFF + u]) * __ldg(&wlin[u]);
        #pragma unroll
        for (int off = 16; off; off >>= 1) s += __shfl_xor_sync(0xffffffffu, s, off);
        if (lane == 0) out[b0 + w] = s + blin[0];
    }
    // keep all CTAs resident until cluster peers stop issuing remote ops
    CL_ARRIVE(); CL_WAIT();
}

// ---------------------------------------------------------------------------
extern "C" void kernel_launch(void* const* d_in, const int* in_sizes, int n_in,
                              void* d_out, int out_size) {
    const float* x    = (const float*)d_in[0];
    const float* wih1 = (const float*)d_in[1];
    const float* whh1 = (const float*)d_in[2];
    const float* bih1 = (const float*)d_in[3];
    const float* bhh1 = (const float*)d_in[4];
    const float* wih2 = (const float*)d_in[5];
    const float* whh2 = (const float*)d_in[6];
    const float* bih2 = (const float*)d_in[7];
    const float* bhh2 = (const float*)d_in[8];
    const float* wlin = (const float*)d_in[9];
    const float* blin = (const float*)d_in[10];
    float* out = (float*)d_out;

    prep_kernel<<<(32 * 2048 + 255) / 256, 256>>>(wih1, whh1, bih1, bhh1,
                                                  wih2, whh2, bih2, bhh2);
    lstm_kernel<<<NCg, NT>>>(x, wlin, blin, out);
}